// round 14
// baseline (speedup 1.0000x reference)
#include <cuda_runtime.h>
#include <cuda_fp16.h>
#include <cstdint>

#define BB 4
#define SS 2048
#define EE 1024
#define HH 16
#define DD 64
#define NTILES 32
#define QROWS 64             // q-rows per CTA in main kernel (4 warps x 16)
#define QRS 128              // q-rows per CTA in sums kernel (4 warps x 32)
#define PKH 72               // Kt pitch in halfs (144B rows): QK B-frag conflict-free
#define PVP 72               // Vs pitch (floats): PV B-frag loads conflict-free
#define PP 68                // Ps pitch (floats): PV A-frag loads conflict-free

static const long long OUT_ELEMS  = (long long)BB * SS * EE;        // 8388608
static const long long ATTN_ELEMS = (long long)BB * HH * SS * SS;   // 268435456

#define FULLM 0xFFFFFFFFu

// per-row normalization constant: log2(1 / sum_k exp(q.k/32))
__device__ float g_logc[BB * HH * SS];

__device__ __forceinline__ uint32_t f2tf(float x) {
    uint32_t r;
    asm("cvt.rna.tf32.f32 %0, %1;" : "=r"(r) : "f"(x));
    return r;
}

__device__ __forceinline__ uint32_t packh2(float x, float y) {
    __half2 h = __floats2half2_rn(x, y);
    uint32_t r;
    memcpy(&r, &h, 4);
    return r;
}

// fp16 mma m16n8k16, fp32 accumulate
__device__ __forceinline__ void mma_f16(float& c0, float& c1, float& c2, float& c3,
                                        uint32_t a0, uint32_t a1, uint32_t a2, uint32_t a3,
                                        uint32_t b0, uint32_t b1)
{
    asm volatile(
        "mma.sync.aligned.m16n8k16.row.col.f32.f16.f16.f32 "
        "{%0,%1,%2,%3}, {%4,%5,%6,%7}, {%8,%9}, {%0,%1,%2,%3};"
        : "+f"(c0), "+f"(c1), "+f"(c2), "+f"(c3)
        : "r"(a0), "r"(a1), "r"(a2), "r"(a3), "r"(b0), "r"(b1));
}

// tf32 mma m16n8k8 (PV path)
__device__ __forceinline__ void mma_tf32(float& c0, float& c1, float& c2, float& c3,
                                         uint32_t a0, uint32_t a1, uint32_t a2, uint32_t a3,
                                         uint32_t b0, uint32_t b1)
{
    asm volatile(
        "mma.sync.aligned.m16n8k8.row.col.f32.tf32.tf32.f32 "
        "{%0,%1,%2,%3}, {%4,%5,%6,%7}, {%8,%9}, {%0,%1,%2,%3};"
        : "+f"(c0), "+f"(c1), "+f"(c2), "+f"(c3)
        : "r"(a0), "r"(a1), "r"(a2), "r"(a3), "r"(b0), "r"(b1));
}

// fp16 A fragments (16 rows): 4 k-blocks x 4 half2 regs
#define LOAD_A16H(A, qg, qr0)                                                     \
    _Pragma("unroll")                                                             \
    for (int kb = 0; kb < 4; kb++) {                                              \
        const float* q0 = qg + (size_t)(qr0)       * EE + kb * 16 + 2 * tid4;     \
        const float* q1 = qg + (size_t)((qr0) + 8) * EE + kb * 16 + 2 * tid4;     \
        A[kb][0] = packh2(q0[0], q0[1]);                                          \
        A[kb][1] = packh2(q1[0], q1[1]);                                          \
        A[kb][2] = packh2(q0[8], q0[9]);                                          \
        A[kb][3] = packh2(q1[8], q1[9]);                                          \
    }

// stage one K row-chunk: float4 (4 dims of key r) -> 4 halfs -> one 8B store
#define STAGE_K_ITER(Kt, kg, r, c4)                                               \
    {                                                                             \
        float4 kv = *(const float4*)((kg) + (size_t)(r) * EE + (c4) * 4);         \
        uint2 hk;                                                                 \
        hk.x = packh2(kv.x, kv.y);                                                \
        hk.y = packh2(kv.z, kv.w);                                                \
        *(uint2*)&(Kt)[(r) * PKH + (c4) * 4] = hk;                                \
    }

extern __shared__ float smem_dyn[];

// ============ Kernel 1: row sums (fp16 QK + exp + reduce only) ============
// 4 warps x 32 q-rows = 128 rows/CTA: B-frag crossbar cost per row halved.
__global__ __launch_bounds__(128, 6)
void attn_sums(const float* __restrict__ q, const float* __restrict__ k)
{
    __half* Kt = (__half*)smem_dyn;    // [64 keys][PKH halfs]

    const int b = blockIdx.z, h = blockIdx.y, qt = blockIdx.x;
    const int t = threadIdx.x, w = t >> 5, lane = t & 31;
    const int gid = lane >> 2, tid4 = lane & 3;
    const float cs = 1.4426950408889634f / 32.0f;   // log2(e)/32
    const int qr0 = w * 32 + gid;

    const float* qg = q + ((size_t)(b * SS + qt * QRS)) * EE + h * DD;
    uint32_t A[4][8];
#pragma unroll
    for (int kb = 0; kb < 4; kb++) {
        const float* q0 = qg + (size_t)qr0        * EE + kb * 16 + 2 * tid4;
        const float* q1 = qg + (size_t)(qr0 + 8)  * EE + kb * 16 + 2 * tid4;
        const float* q2 = qg + (size_t)(qr0 + 16) * EE + kb * 16 + 2 * tid4;
        const float* q3 = qg + (size_t)(qr0 + 24) * EE + kb * 16 + 2 * tid4;
        A[kb][0] = packh2(q0[0], q0[1]);
        A[kb][1] = packh2(q1[0], q1[1]);
        A[kb][2] = packh2(q0[8], q0[9]);
        A[kb][3] = packh2(q1[8], q1[9]);
        A[kb][4] = packh2(q2[0], q2[1]);
        A[kb][5] = packh2(q3[0], q3[1]);
        A[kb][6] = packh2(q2[8], q2[9]);
        A[kb][7] = packh2(q3[8], q3[9]);
    }

    const float* kg0 = k + ((size_t)b * SS) * EE + h * DD;
    float lp[4] = {0.f, 0.f, 0.f, 0.f};

    for (int kt = 0; kt < NTILES; kt++) {
        const float* kg = kg0 + (size_t)kt * 64 * EE;
        for (int i = t; i < 1024; i += 128) {
            int r = i >> 4, c4 = i & 15;
            STAGE_K_ITER(Kt, kg, r, c4)
        }
        __syncthreads();

#pragma unroll
        for (int nb = 0; nb < 8; nb++) {
            float S[8] = {0.f,0.f,0.f,0.f,0.f,0.f,0.f,0.f};
#pragma unroll
            for (int kb = 0; kb < 4; kb++) {
                uint32_t b0 = *(const uint32_t*)&Kt[(nb * 8 + gid) * PKH + kb * 16 + 2 * tid4];
                uint32_t b1 = *(const uint32_t*)&Kt[(nb * 8 + gid) * PKH + kb * 16 + 2 * tid4 + 8];
                mma_f16(S[0], S[1], S[2], S[3],
                        A[kb][0], A[kb][1], A[kb][2], A[kb][3], b0, b1);
                mma_f16(S[4], S[5], S[6], S[7],
                        A[kb][4], A[kb][5], A[kb][6], A[kb][7], b0, b1);
            }
            lp[0] += exp2f(S[0] * cs) + exp2f(S[1] * cs);
            lp[1] += exp2f(S[2] * cs) + exp2f(S[3] * cs);
            lp[2] += exp2f(S[4] * cs) + exp2f(S[5] * cs);
            lp[3] += exp2f(S[6] * cs) + exp2f(S[7] * cs);
        }
        __syncthreads();
    }

#pragma unroll
    for (int i = 0; i < 4; i++) {
        lp[i] += __shfl_xor_sync(FULLM, lp[i], 1);
        lp[i] += __shfl_xor_sync(FULLM, lp[i], 2);
    }
    if (tid4 == 0) {
        size_t base = (size_t)((b * HH + h) * SS) + (size_t)qt * QRS;
#pragma unroll
        for (int i = 0; i < 4; i++)
            g_logc[base + qr0 + 8 * i] = -log2f(lp[i]);
    }
}

// ============ Kernel 2: normalized attn + O ============
// fp16 QK -> fp32 P -> attn STG direct from registers; Ps smem feeds tf32 PV.
__global__ __launch_bounds__(128, 5)
void attn_main(const float* __restrict__ q, const float* __restrict__ k,
               const float* __restrict__ v, float* __restrict__ out,
               float* __restrict__ attn, int write_attn)
{
    __half* Kt = (__half*)smem_dyn;                 // [64 keys][PKH halfs]  9216 B
    float*  Vs = smem_dyn + (64 * PKH) / 2;         // [64 keys][PVP floats] 18432 B
    float*  Ps = Vs + 64 * PVP;                     // [64 q][PP floats]     17408 B

    const int b = blockIdx.z, h = blockIdx.y, qt = blockIdx.x;
    const int t = threadIdx.x, w = t >> 5, lane = t & 31;
    const int gid = lane >> 2, tid4 = lane & 3;
    const float cs = 1.4426950408889634f / 32.0f;
    const int qr0 = w * 16 + gid;

    const float* qg = q + ((size_t)(b * SS + qt * QROWS)) * EE + h * DD;
    uint32_t A[4][4];
    LOAD_A16H(A, qg, qr0)

    float c0add, c1add;
    {
        size_t base = (size_t)((b * HH + h) * SS) + (size_t)qt * QROWS;
        c0add = g_logc[base + qr0];
        c1add = g_logc[base + qr0 + 8];
    }

    float Oacc[8][4];
#pragma unroll
    for (int nb = 0; nb < 8; nb++)
#pragma unroll
        for (int j = 0; j < 4; j++) Oacc[nb][j] = 0.f;

    const float* kg0 = k + ((size_t)b * SS) * EE + h * DD;
    const float* vg0 = v + ((size_t)b * SS) * EE + h * DD;
    float* attng = attn + ((size_t)((b * HH + h) * SS) + (size_t)qt * QROWS) * SS;

    for (int kt = 0; kt < NTILES; kt++) {
        const float* kg = kg0 + (size_t)kt * 64 * EE;
        const float* vg = vg0 + (size_t)kt * 64 * EE;
        for (int i = t; i < 1024; i += 128) {
            int r = i >> 4, c4 = i & 15;
            STAGE_K_ITER(Kt, kg, r, c4)
            float4 vv = *(const float4*)(vg + (size_t)r * EE + c4 * 4);
            float4 vo;
            vo.x = __uint_as_float(f2tf(vv.x));
            vo.y = __uint_as_float(f2tf(vv.y));
            vo.z = __uint_as_float(f2tf(vv.z));
            vo.w = __uint_as_float(f2tf(vv.w));
            *(float4*)&Vs[r * PVP + c4 * 4] = vo;
        }
        __syncthreads();

        // ---- QK (fp16, nb-outer) + normalized exp -> Ps + direct attn STG ----
#pragma unroll
        for (int nb = 0; nb < 8; nb++) {
            float S[4] = {0.f, 0.f, 0.f, 0.f};
#pragma unroll
            for (int kb = 0; kb < 4; kb++) {
                uint32_t b0 = *(const uint32_t*)&Kt[(nb * 8 + gid) * PKH + kb * 16 + 2 * tid4];
                uint32_t b1 = *(const uint32_t*)&Kt[(nb * 8 + gid) * PKH + kb * 16 + 2 * tid4 + 8];
                mma_f16(S[0], S[1], S[2], S[3],
                        A[kb][0], A[kb][1], A[kb][2], A[kb][3], b0, b1);
            }
            float p0 = exp2f(fmaf(S[0], cs, c0add));
            float p1 = exp2f(fmaf(S[1], cs, c0add));
            float p2 = exp2f(fmaf(S[2], cs, c1add));
            float p3 = exp2f(fmaf(S[3], cs, c1add));
            *(float2*)&Ps[(size_t)qr0       * PP + nb * 8 + 2 * tid4] = make_float2(p0, p1);
            *(float2*)&Ps[(size_t)(qr0 + 8) * PP + nb * 8 + 2 * tid4] = make_float2(p2, p3);
            if (write_attn) {
                float* ag = attng + kt * 64 + nb * 8 + 2 * tid4;
                *(float2*)(ag + (size_t)qr0       * SS) = make_float2(p0, p1);
                *(float2*)(ag + (size_t)(qr0 + 8) * SS) = make_float2(p2, p3);
            }
        }
        // warp-private Ps rows: no barrier needed before PV.

        // ---- O += P V (tf32) ----
#pragma unroll
        for (int kb = 0; kb < 8; kb++) {
            uint32_t pa0 = f2tf(Ps[(size_t)qr0       * PP + kb * 8 + tid4]);
            uint32_t pa1 = f2tf(Ps[(size_t)(qr0 + 8) * PP + kb * 8 + tid4]);
            uint32_t pa2 = f2tf(Ps[(size_t)qr0       * PP + kb * 8 + tid4 + 4]);
            uint32_t pa3 = f2tf(Ps[(size_t)(qr0 + 8) * PP + kb * 8 + tid4 + 4]);
#pragma unroll
            for (int nb = 0; nb < 8; nb++) {
                uint32_t b0 = __float_as_uint(Vs[(kb * 8 + tid4)     * PVP + nb * 8 + gid]);
                uint32_t b1 = __float_as_uint(Vs[(kb * 8 + tid4 + 4) * PVP + nb * 8 + gid]);
                mma_tf32(Oacc[nb][0], Oacc[nb][1], Oacc[nb][2], Oacc[nb][3],
                         pa0, pa1, pa2, pa3, b0, b1);
            }
        }
        __syncthreads();   // protect Kt/Vs/Ps restage
    }

    // ---- out = O (already normalized) ----
    float* og = out + ((size_t)(b * SS + qt * QROWS)) * EE + h * DD;
#pragma unroll
    for (int nb = 0; nb < 8; nb++) {
        *(float2*)(og + (size_t)qr0       * EE + nb * 8 + 2 * tid4) =
            make_float2(Oacc[nb][0], Oacc[nb][1]);
        *(float2*)(og + (size_t)(qr0 + 8) * EE + nb * 8 + 2 * tid4) =
            make_float2(Oacc[nb][2], Oacc[nb][3]);
    }
}

static const size_t SHMEM_SUMS = (size_t)64 * PKH * sizeof(__half);                         // 9216
static const size_t SHMEM_MAIN = (size_t)64 * PKH * sizeof(__half)
                               + (size_t)64 * (PVP + PP) * sizeof(float);                   // 45056

static bool setup_once()
{
    cudaFuncSetAttribute(attn_sums, cudaFuncAttributeMaxDynamicSharedMemorySize,
                         (int)SHMEM_SUMS);
    cudaFuncSetAttribute(attn_main, cudaFuncAttributeMaxDynamicSharedMemorySize,
                         (int)SHMEM_MAIN);
    return true;
}

extern "C" void kernel_launch(void* const* d_in, const int* in_sizes, int n_in,
                              void* d_out, int out_size)
{
    static bool ready = setup_once();
    (void)ready;

    const float* q = (const float*)d_in[0];
    const float* k = (const float*)d_in[1];
    const float* v = (const float*)d_in[2];
    float* out  = (float*)d_out;
    float* attn = out + OUT_ELEMS;

    const long long need = OUT_ELEMS + ATTN_ELEMS;
    const int write_attn = ((long long)out_size >= need) ? 1 : 0;

    dim3 gridS(SS / QRS, HH, BB);
    attn_sums<<<gridS, 128, SHMEM_SUMS>>>(q, k);
    dim3 gridM(SS / QROWS, HH, BB);
    attn_main<<<gridM, 128, SHMEM_MAIN>>>(q, k, v, out, attn, write_attn);
}

// round 15
// speedup vs baseline: 1.1722x; 1.1722x over previous
#include <cuda_runtime.h>
#include <cuda_fp16.h>
#include <cstdint>

#define BB 4
#define SS 2048
#define EE 1024
#define HH 16
#define DD 64
#define NTILES 32
#define QROWS 64             // q-rows per CTA in main kernel (4 warps x 16)
#define QRS 128              // q-rows per CTA in sums kernel (4 warps x 32)
#define PKH 72               // Kt pitch in halfs (144B rows): QK B-frag conflict-free
#define PVH 72               // Vh pitch in halfs (144B rows): LDSM rows conflict-free
#define PP 68                // Ps pitch (floats): attn-store reads conflict-free

static const long long OUT_ELEMS  = (long long)BB * SS * EE;        // 8388608
static const long long ATTN_ELEMS = (long long)BB * HH * SS * SS;   // 268435456

#define FULLM 0xFFFFFFFFu

// per-row normalization constant: log2(1 / sum_k exp(q.k/32))
__device__ float g_logc[BB * HH * SS];

__device__ __forceinline__ uint32_t packh2(float x, float y) {
    __half2 h = __floats2half2_rn(x, y);
    uint32_t r;
    memcpy(&r, &h, 4);
    return r;
}

__device__ __forceinline__ uint32_t smem_u32(const void* p) {
    uint32_t a;
    asm("{ .reg .u64 t; cvta.to.shared.u64 t, %1; cvt.u32.u64 %0, t; }"
        : "=r"(a) : "l"(p));
    return a;
}

// fp16 mma m16n8k16, fp32 accumulate
__device__ __forceinline__ void mma_f16(float& c0, float& c1, float& c2, float& c3,
                                        uint32_t a0, uint32_t a1, uint32_t a2, uint32_t a3,
                                        uint32_t b0, uint32_t b1)
{
    asm volatile(
        "mma.sync.aligned.m16n8k16.row.col.f32.f16.f16.f32 "
        "{%0,%1,%2,%3}, {%4,%5,%6,%7}, {%8,%9}, {%0,%1,%2,%3};"
        : "+f"(c0), "+f"(c1), "+f"(c2), "+f"(c3)
        : "r"(a0), "r"(a1), "r"(a2), "r"(a3), "r"(b0), "r"(b1));
}

__device__ __forceinline__ void ldsm_x4_trans(uint32_t& r0, uint32_t& r1,
                                              uint32_t& r2, uint32_t& r3, uint32_t addr)
{
    asm volatile(
        "ldmatrix.sync.aligned.m8n8.x4.trans.shared.b16 {%0,%1,%2,%3}, [%4];"
        : "=r"(r0), "=r"(r1), "=r"(r2), "=r"(r3) : "r"(addr));
}

// fp16 A fragments (16 rows): 4 k-blocks x 4 half2 regs
#define LOAD_A16H(A, qg, qr0)                                                     \
    _Pragma("unroll")                                                             \
    for (int kb = 0; kb < 4; kb++) {                                              \
        const float* q0 = qg + (size_t)(qr0)       * EE + kb * 16 + 2 * tid4;     \
        const float* q1 = qg + (size_t)((qr0) + 8) * EE + kb * 16 + 2 * tid4;     \
        A[kb][0] = packh2(q0[0], q0[1]);                                          \
        A[kb][1] = packh2(q1[0], q1[1]);                                          \
        A[kb][2] = packh2(q0[8], q0[9]);                                          \
        A[kb][3] = packh2(q1[8], q1[9]);                                          \
    }

// stage one fp16 row-chunk: float4 (4 dims of row r) -> 4 halfs -> one 8B store
#define STAGE_H_ITER(Dst, src, r, c4, pitch)                                      \
    {                                                                             \
        float4 kv = *(const float4*)((src) + (size_t)(r) * EE + (c4) * 4);        \
        uint2 hk;                                                                 \
        hk.x = packh2(kv.x, kv.y);                                                \
        hk.y = packh2(kv.z, kv.w);                                                \
        *(uint2*)&(Dst)[(r) * (pitch) + (c4) * 4] = hk;                           \
    }

extern __shared__ float smem_dyn[];

// ============ Kernel 1: row sums (fp16 QK + exp + reduce only) ============
// 4 warps x 32 q-rows = 128 rows/CTA.
__global__ __launch_bounds__(128, 6)
void attn_sums(const float* __restrict__ q, const float* __restrict__ k)
{
    __half* Kt = (__half*)smem_dyn;    // [64 keys][PKH halfs]

    const int b = blockIdx.z, h = blockIdx.y, qt = blockIdx.x;
    const int t = threadIdx.x, w = t >> 5, lane = t & 31;
    const int gid = lane >> 2, tid4 = lane & 3;
    const float cs = 1.4426950408889634f / 32.0f;   // log2(e)/32
    const int qr0 = w * 32 + gid;

    const float* qg = q + ((size_t)(b * SS + qt * QRS)) * EE + h * DD;
    uint32_t A[4][8];
#pragma unroll
    for (int kb = 0; kb < 4; kb++) {
        const float* q0 = qg + (size_t)qr0        * EE + kb * 16 + 2 * tid4;
        const float* q1 = qg + (size_t)(qr0 + 8)  * EE + kb * 16 + 2 * tid4;
        const float* q2 = qg + (size_t)(qr0 + 16) * EE + kb * 16 + 2 * tid4;
        const float* q3 = qg + (size_t)(qr0 + 24) * EE + kb * 16 + 2 * tid4;
        A[kb][0] = packh2(q0[0], q0[1]);
        A[kb][1] = packh2(q1[0], q1[1]);
        A[kb][2] = packh2(q0[8], q0[9]);
        A[kb][3] = packh2(q1[8], q1[9]);
        A[kb][4] = packh2(q2[0], q2[1]);
        A[kb][5] = packh2(q3[0], q3[1]);
        A[kb][6] = packh2(q2[8], q2[9]);
        A[kb][7] = packh2(q3[8], q3[9]);
    }

    const float* kg0 = k + ((size_t)b * SS) * EE + h * DD;
    float lp[4] = {0.f, 0.f, 0.f, 0.f};

    for (int kt = 0; kt < NTILES; kt++) {
        const float* kg = kg0 + (size_t)kt * 64 * EE;
        for (int i = t; i < 1024; i += 128) {
            int r = i >> 4, c4 = i & 15;
            STAGE_H_ITER(Kt, kg, r, c4, PKH)
        }
        __syncthreads();

#pragma unroll
        for (int nb = 0; nb < 8; nb++) {
            float S[8] = {0.f,0.f,0.f,0.f,0.f,0.f,0.f,0.f};
#pragma unroll
            for (int kb = 0; kb < 4; kb++) {
                uint32_t b0 = *(const uint32_t*)&Kt[(nb * 8 + gid) * PKH + kb * 16 + 2 * tid4];
                uint32_t b1 = *(const uint32_t*)&Kt[(nb * 8 + gid) * PKH + kb * 16 + 2 * tid4 + 8];
                mma_f16(S[0], S[1], S[2], S[3],
                        A[kb][0], A[kb][1], A[kb][2], A[kb][3], b0, b1);
                mma_f16(S[4], S[5], S[6], S[7],
                        A[kb][4], A[kb][5], A[kb][6], A[kb][7], b0, b1);
            }
            lp[0] += exp2f(S[0] * cs) + exp2f(S[1] * cs);
            lp[1] += exp2f(S[2] * cs) + exp2f(S[3] * cs);
            lp[2] += exp2f(S[4] * cs) + exp2f(S[5] * cs);
            lp[3] += exp2f(S[6] * cs) + exp2f(S[7] * cs);
        }
        __syncthreads();
    }

#pragma unroll
    for (int i = 0; i < 4; i++) {
        lp[i] += __shfl_xor_sync(FULLM, lp[i], 1);
        lp[i] += __shfl_xor_sync(FULLM, lp[i], 2);
    }
    if (tid4 == 0) {
        size_t base = (size_t)((b * HH + h) * SS) + (size_t)qt * QRS;
#pragma unroll
        for (int i = 0; i < 4; i++)
            g_logc[base + qr0 + 8 * i] = -log2f(lp[i]);
    }
}

// ============ Kernel 2: normalized attn + O ============
// fp16 QK -> P (fp32 in Ps for attn; half2 in regs as PV A-frags) ->
// fp16 PV with ldmatrix.trans B-frags. attn stored coalesced from Ps.
__global__ __launch_bounds__(128, 5)
void attn_main(const float* __restrict__ q, const float* __restrict__ k,
               const float* __restrict__ v, float* __restrict__ out,
               float* __restrict__ attn, int write_attn)
{
    __half* Kt = (__half*)smem_dyn;                       // [64 keys][PKH]  9216 B
    __half* Vh = (__half*)smem_dyn + 64 * PKH;            // [64 keys][PVH]  9216 B
    float*  Ps = smem_dyn + (64 * (PKH + PVH)) / 2;       // [64 q][PP]      17408 B

    const int b = blockIdx.z, h = blockIdx.y, qt = blockIdx.x;
    const int t = threadIdx.x, w = t >> 5, lane = t & 31;
    const int gid = lane >> 2, tid4 = lane & 3;
    const float cs = 1.4426950408889634f / 32.0f;
    const int qr0 = w * 16 + gid;

    // ldmatrix.x4.trans lane addressing into Vh:
    //   matrix l>>3: 0 -> keys k0..k0+7 dims n0..n0+7,  1 -> keys +8,
    //                2 -> dims n0+8,                    3 -> keys+8, dims n0+8
    const uint32_t vbase = smem_u32(Vh);
    const int ld_row = (lane & 7) + 8 * ((lane >> 3) & 1);   // key offset within 16
    const int ld_col = 16 * (lane >> 4);                     // dim byte offset (+8 dims)

    const float* qg = q + ((size_t)(b * SS + qt * QROWS)) * EE + h * DD;
    uint32_t A[4][4];
    LOAD_A16H(A, qg, qr0)

    float c0add, c1add;
    {
        size_t base = (size_t)((b * HH + h) * SS) + (size_t)qt * QROWS;
        c0add = g_logc[base + qr0];
        c1add = g_logc[base + qr0 + 8];
    }

    float Oacc[8][4];
#pragma unroll
    for (int nb = 0; nb < 8; nb++)
#pragma unroll
        for (int j = 0; j < 4; j++) Oacc[nb][j] = 0.f;

    const float* kg0 = k + ((size_t)b * SS) * EE + h * DD;
    const float* vg0 = v + ((size_t)b * SS) * EE + h * DD;
    float* attng = attn + ((size_t)((b * HH + h) * SS) + (size_t)qt * QROWS) * SS;

    for (int kt = 0; kt < NTILES; kt++) {
        const float* kg = kg0 + (size_t)kt * 64 * EE;
        const float* vg = vg0 + (size_t)kt * 64 * EE;
        for (int i = t; i < 1024; i += 128) {
            int r = i >> 4, c4 = i & 15;
            STAGE_H_ITER(Kt, kg, r, c4, PKH)
            STAGE_H_ITER(Vh, vg, r, c4, PVH)
        }
        __syncthreads();

        // ---- QK (fp16, nb-outer): P -> Ps (for attn) + half2 regs (PV A-frags) ----
        uint32_t Ph0[8], Ph1[8];
#pragma unroll
        for (int nb = 0; nb < 8; nb++) {
            float S[4] = {0.f, 0.f, 0.f, 0.f};
#pragma unroll
            for (int kb = 0; kb < 4; kb++) {
                uint32_t b0 = *(const uint32_t*)&Kt[(nb * 8 + gid) * PKH + kb * 16 + 2 * tid4];
                uint32_t b1 = *(const uint32_t*)&Kt[(nb * 8 + gid) * PKH + kb * 16 + 2 * tid4 + 8];
                mma_f16(S[0], S[1], S[2], S[3],
                        A[kb][0], A[kb][1], A[kb][2], A[kb][3], b0, b1);
            }
            float p0 = exp2f(fmaf(S[0], cs, c0add));
            float p1 = exp2f(fmaf(S[1], cs, c0add));
            float p2 = exp2f(fmaf(S[2], cs, c1add));
            float p3 = exp2f(fmaf(S[3], cs, c1add));
            *(float2*)&Ps[(size_t)qr0       * PP + nb * 8 + 2 * tid4] = make_float2(p0, p1);
            *(float2*)&Ps[(size_t)(qr0 + 8) * PP + nb * 8 + 2 * tid4] = make_float2(p2, p3);
            Ph0[nb] = packh2(p0, p1);       // A-frag rows qr0
            Ph1[nb] = packh2(p2, p3);       // A-frag rows qr0+8
        }
        // warp-private Ps rows: no barrier needed before attn store.

        // ---- attn store (coalesced float4 from Ps, round-13 pattern) ----
        if (write_attn) {
            float* ag = attng + kt * 64;
            for (int i = lane; i < 256; i += 32) {
                int r = w * 16 + (i >> 4), c4 = i & 15;
                *(float4*)(ag + (size_t)r * SS + c4 * 4) = *(const float4*)&Ps[r * PP + c4 * 4];
            }
        }

        // ---- O += P V (fp16): A from regs, B via ldmatrix.trans ----
#pragma unroll
        for (int kb = 0; kb < 4; kb++) {
            uint32_t a0 = Ph0[2 * kb],     a1 = Ph1[2 * kb];
            uint32_t a2 = Ph0[2 * kb + 1], a3 = Ph1[2 * kb + 1];
            uint32_t rowoff = (uint32_t)(16 * kb + ld_row) * (PVH * 2) + ld_col;
#pragma unroll
            for (int np = 0; np < 4; np++) {            // dims n0 = 16*np
                uint32_t b0, b1, b2, b3;
                ldsm_x4_trans(b0, b1, b2, b3, vbase + rowoff + 32 * np);
                mma_f16(Oacc[2 * np][0], Oacc[2 * np][1], Oacc[2 * np][2], Oacc[2 * np][3],
                        a0, a1, a2, a3, b0, b1);
                mma_f16(Oacc[2 * np + 1][0], Oacc[2 * np + 1][1],
                        Oacc[2 * np + 1][2], Oacc[2 * np + 1][3],
                        a0, a1, a2, a3, b2, b3);
            }
        }
        __syncthreads();   // protect Kt/Vh/Ps restage
    }

    // ---- out = O (already normalized) ----
    float* og = out + ((size_t)(b * SS + qt * QROWS)) * EE + h * DD;
#pragma unroll
    for (int nb = 0; nb < 8; nb++) {
        *(float2*)(og + (size_t)qr0       * EE + nb * 8 + 2 * tid4) =
            make_float2(Oacc[nb][0], Oacc[nb][1]);
        *(float2*)(og + (size_t)(qr0 + 8) * EE + nb * 8 + 2 * tid4) =
            make_float2(Oacc[nb][2], Oacc[nb][3]);
    }
}

static const size_t SHMEM_SUMS = (size_t)64 * PKH * sizeof(__half);                         // 9216
static const size_t SHMEM_MAIN = (size_t)64 * (PKH + PVH) * sizeof(__half)
                               + (size_t)64 * PP * sizeof(float);                           // 35840

static bool setup_once()
{
    cudaFuncSetAttribute(attn_sums, cudaFuncAttributeMaxDynamicSharedMemorySize,
                         (int)SHMEM_SUMS);
    cudaFuncSetAttribute(attn_main, cudaFuncAttributeMaxDynamicSharedMemorySize,
                         (int)SHMEM_MAIN);
    return true;
}

extern "C" void kernel_launch(void* const* d_in, const int* in_sizes, int n_in,
                              void* d_out, int out_size)
{
    static bool ready = setup_once();
    (void)ready;

    const float* q = (const float*)d_in[0];
    const float* k = (const float*)d_in[1];
    const float* v = (const float*)d_in[2];
    float* out  = (float*)d_out;
    float* attn = out + OUT_ELEMS;

    const long long need = OUT_ELEMS + ATTN_ELEMS;
    const int write_attn = ((long long)out_size >= need) ? 1 : 0;

    dim3 gridS(SS / QRS, HH, BB);
    attn_sums<<<gridS, 128, SHMEM_SUMS>>>(q, k);
    dim3 gridM(SS / QROWS, HH, BB);
    attn_main<<<gridM, 128, SHMEM_MAIN>>>(q, k, v, out, attn, write_attn);
}